// round 1
// baseline (speedup 1.0000x reference)
#include <cuda_runtime.h>
#include <cuda_bf16.h>
#include <cstdint>

// Problem constants
#define B_  64
#define S_  2048
#define E_  256
#define H_  256

// Scratch (device-global: runtime allocation is forbidden)
__device__ float g_xw[(size_t)B_ * S_ * H_];   // 128 MB: xw[b,s,h] = x@Ww^T + Wb
__device__ float g_UwT[H_ * H_];               // UwT[k][h] = Uw[h][k]

// ---------------------------------------------------------------------------
// Kernel 0: transpose Uw (tiny, 256x256)
// ---------------------------------------------------------------------------
__global__ void transpose256(const float* __restrict__ A) {
    int k = blockIdx.x;
    int h = threadIdx.x;
    g_UwT[k * H_ + h] = A[h * H_ + k];
}

// ---------------------------------------------------------------------------
// Kernel 1: xw = X[131072,256] @ Ww^T[256,256] + Wb
// Tiled fp32 GEMM: 64x64 block tile, K-chunk 16, 256 threads, 4x4 microtile.
// ---------------------------------------------------------------------------
#define TM 64
#define TN 64
#define TK 16
#define PAD 4   // row stride 68 floats = 272B, 16B-aligned

__global__ __launch_bounds__(256) void gemm_xw(const float* __restrict__ x,
                                               const float* __restrict__ Ww,
                                               const float* __restrict__ Wb) {
    __shared__ float As[TK][TM + PAD];
    __shared__ float Bs[TK][TN + PAD];

    const int t  = threadIdx.x;
    const int tx = t & 15;        // 0..15 -> n microtile
    const int ty = t >> 4;        // 0..15 -> m microtile
    const size_t i0 = (size_t)blockIdx.y * TM;   // row block in [0,131072)
    const int    h0 = blockIdx.x * TN;           // col block in [0,256)

    float acc[4][4] = {};

    for (int k0 = 0; k0 < E_; k0 += TK) {
        // Cooperative load: 64x16 A-tile and 64x16 B-tile (1024 elems each, 4/thread)
        #pragma unroll
        for (int it = 0; it < 4; it++) {
            int id = t + it * 256;
            int k  = id & (TK - 1);
            int m  = id >> 4;          // id / 16
            As[k][m] = x[(i0 + m) * E_ + k0 + k];
            Bs[k][m] = Ww[(size_t)(h0 + m) * E_ + k0 + k];
        }
        __syncthreads();

        #pragma unroll
        for (int k = 0; k < TK; k++) {
            float4 a = *(const float4*)&As[k][ty * 4];
            float4 b = *(const float4*)&Bs[k][tx * 4];
            acc[0][0] += a.x * b.x; acc[0][1] += a.x * b.y; acc[0][2] += a.x * b.z; acc[0][3] += a.x * b.w;
            acc[1][0] += a.y * b.x; acc[1][1] += a.y * b.y; acc[1][2] += a.y * b.z; acc[1][3] += a.y * b.w;
            acc[2][0] += a.z * b.x; acc[2][1] += a.z * b.y; acc[2][2] += a.z * b.z; acc[2][3] += a.z * b.w;
            acc[3][0] += a.w * b.x; acc[3][1] += a.w * b.y; acc[3][2] += a.w * b.z; acc[3][3] += a.w * b.w;
        }
        __syncthreads();
    }

    #pragma unroll
    for (int r = 0; r < 4; r++) {
        #pragma unroll
        for (int c = 0; c < 4; c++) {
            int h = h0 + tx * 4 + c;
            g_xw[(i0 + ty * 4 + r) * H_ + h] = acc[r][c] + Wb[h];
        }
    }
}

// ---------------------------------------------------------------------------
// Kernel 2: sequential scan. One CTA per batch element, 256 threads.
// Thread tid owns output h = tid. Uw row split: k in [0,UREG) register-resident,
// k in [UREG,256) streamed from L1-resident transposed UwT (coalesced).
// ---------------------------------------------------------------------------
#define UREG 160

__global__ __launch_bounds__(256, 1) void rnn_scan(const float* __restrict__ Ub,
                                                   float* __restrict__ Out,     // [B,S,H]
                                                   float* __restrict__ Tfin) {  // [B,H]
    __shared__ float vsm[2][H_];

    const int tid = threadIdx.x;
    const int b   = blockIdx.x;

    // Register-cache first UREG rows of UwT (= Uw[tid][0..UREG))  — coalesced loads
    float uw[UREG];
    #pragma unroll
    for (int j = 0; j < UREG; j++)
        uw[j] = g_UwT[j * H_ + tid];

    const float ub = Ub[tid];
    float t = 0.0f;

    const float* xwp = g_xw + (size_t)b * S_ * H_ + tid;
    float*       op  = Out  + (size_t)b * S_ * H_ + tid;

    float xv = __ldcs(xwp);   // streaming load (evict-first: keep UwT in L1)

    for (int s = 0; s < S_; s++) {
        float v = tanhf(xv + t);
        float* vb = vsm[s & 1];
        vb[tid] = v;
        __syncthreads();

        // Prefetch next step's xw early (hidden behind ~1100-cycle dot)
        if (s + 1 < S_) xv = __ldcs(xwp + (size_t)(s + 1) * H_);

        float a0 = ub, a1 = 0.0f, a2 = 0.0f, a3 = 0.0f;
        const float* vs = vb;

        // Register half: 160 FMAs, v via broadcast LDS.128
        #pragma unroll
        for (int j = 0; j < UREG; j += 4) {
            float4 vv = *(const float4*)(vs + j);
            a0 += uw[j + 0] * vv.x;
            a1 += uw[j + 1] * vv.y;
            a2 += uw[j + 2] * vv.z;
            a3 += uw[j + 3] * vv.w;
        }
        // L1 half: 96 coalesced scalar LDGs from UwT rows [UREG,256) (L1-resident, 96KB)
        #pragma unroll 8
        for (int j = UREG; j < H_; j += 4) {
            float4 vv = *(const float4*)(vs + j);
            a0 += g_UwT[(j + 0) * H_ + tid] * vv.x;
            a1 += g_UwT[(j + 1) * H_ + tid] * vv.y;
            a2 += g_UwT[(j + 2) * H_ + tid] * vv.z;
            a3 += g_UwT[(j + 3) * H_ + tid] * vv.w;
        }

        t = (a0 + a1) + (a2 + a3);
        op[(size_t)s * H_] = t;
        // no second sync needed: double-buffered vsm + the single barrier above
    }

    Tfin[b * H_ + tid] = t;
}

// ---------------------------------------------------------------------------
// Launcher
// ---------------------------------------------------------------------------
extern "C" void kernel_launch(void* const* d_in, const int* in_sizes, int n_in,
                              void* d_out, int out_size) {
    const float* x  = (const float*)d_in[0];   // [B,S,E]
    const float* Ww = (const float*)d_in[1];   // [H,E]
    const float* Wb = (const float*)d_in[2];   // [H]
    const float* Uw = (const float*)d_in[3];   // [H,H]
    const float* Ub = (const float*)d_in[4];   // [H]

    float* out  = (float*)d_out;
    float* tfin = out;                          // [B,H]   (tuple element 0)
    float* O    = out + (size_t)B_ * H_;        // [B,S,H] (tuple element 1)

    transpose256<<<H_, H_>>>(Uw);
    gemm_xw<<<dim3(H_ / TN, (B_ * S_) / TM), 256>>>(x, Ww, Wb);
    rnn_scan<<<B_, 256>>>(Ub, O, tfin);
}

// round 2
// speedup vs baseline: 2.1001x; 2.1001x over previous
#include <cuda_runtime.h>
#include <cuda_bf16.h>
#include <cstdint>

// Problem constants
#define B_  64
#define S_  2048
#define E_  256
#define H_  256

// Scratch (device-global: runtime allocation is forbidden)
__device__ float g_xw[(size_t)B_ * S_ * H_];   // 128 MB: xw[b,s,h] = x@Ww^T + Wb
__device__ float g_UwT[H_ * H_];               // UwT[k][h] = Uw[h][k]

// ---------------------------------------------------------------------------
// Kernel 0: transpose Uw (tiny, 256x256)
// ---------------------------------------------------------------------------
__global__ void transpose256(const float* __restrict__ A) {
    int k = blockIdx.x;
    int h = threadIdx.x;
    g_UwT[k * H_ + h] = A[h * H_ + k];
}

// ---------------------------------------------------------------------------
// Kernel 1: xw = X[131072,256] @ Ww^T[256,256] + Wb
// 128x64 block tile, K-chunk 16, 256 threads, 8x4 microtile,
// float4 global loads, register double-buffering of the next tile.
// ---------------------------------------------------------------------------
#define GTM 128
#define GTN 64
#define GTK 16
#define GPAD 4

__global__ __launch_bounds__(256) void gemm_xw(const float* __restrict__ x,
                                               const float* __restrict__ Ww,
                                               const float* __restrict__ Wb) {
    __shared__ float As[GTK][GTM + GPAD];
    __shared__ float Bs[GTK][GTN + GPAD];

    const int t  = threadIdx.x;
    const int tx = t & 15;         // n microtile: 4 cols
    const int ty = t >> 4;         // m microtile: 8 rows
    const size_t i0 = (size_t)blockIdx.y * GTM;
    const int    h0 = blockIdx.x * GTN;

    // Global-load coordinates (float4 along k)
    const int am0 = (t + 0)   >> 2, akq0 = (t + 0)   & 3;
    const int am1 = (t + 256) >> 2, akq1 = (t + 256) & 3;
    const int bn  = t >> 2,         bkq  = t & 3;

    float4 ra0, ra1, rb;

    // Preload chunk 0
    ra0 = *(const float4*)&x [(i0 + am0) * E_ + akq0 * 4];
    ra1 = *(const float4*)&x [(i0 + am1) * E_ + akq1 * 4];
    rb  = *(const float4*)&Ww[(size_t)(h0 + bn) * E_ + bkq * 4];

    float acc[8][4] = {};

    for (int k0 = 0; k0 < E_; k0 += GTK) {
        // regs -> smem (scatter the float4 k-quads)
        As[akq0 * 4 + 0][am0] = ra0.x; As[akq0 * 4 + 1][am0] = ra0.y;
        As[akq0 * 4 + 2][am0] = ra0.z; As[akq0 * 4 + 3][am0] = ra0.w;
        As[akq1 * 4 + 0][am1] = ra1.x; As[akq1 * 4 + 1][am1] = ra1.y;
        As[akq1 * 4 + 2][am1] = ra1.z; As[akq1 * 4 + 3][am1] = ra1.w;
        Bs[bkq  * 4 + 0][bn]  = rb.x;  Bs[bkq  * 4 + 1][bn]  = rb.y;
        Bs[bkq  * 4 + 2][bn]  = rb.z;  Bs[bkq  * 4 + 3][bn]  = rb.w;
        __syncthreads();

        // Prefetch next chunk into registers while computing this one
        if (k0 + GTK < E_) {
            const int kn = k0 + GTK;
            ra0 = *(const float4*)&x [(i0 + am0) * E_ + kn + akq0 * 4];
            ra1 = *(const float4*)&x [(i0 + am1) * E_ + kn + akq1 * 4];
            rb  = *(const float4*)&Ww[(size_t)(h0 + bn) * E_ + kn + bkq * 4];
        }

        #pragma unroll
        for (int k = 0; k < GTK; k++) {
            float4 a0 = *(const float4*)&As[k][ty * 8 + 0];
            float4 a1 = *(const float4*)&As[k][ty * 8 + 4];
            float4 b  = *(const float4*)&Bs[k][tx * 4];
            acc[0][0] += a0.x * b.x; acc[0][1] += a0.x * b.y; acc[0][2] += a0.x * b.z; acc[0][3] += a0.x * b.w;
            acc[1][0] += a0.y * b.x; acc[1][1] += a0.y * b.y; acc[1][2] += a0.y * b.z; acc[1][3] += a0.y * b.w;
            acc[2][0] += a0.z * b.x; acc[2][1] += a0.z * b.y; acc[2][2] += a0.z * b.z; acc[2][3] += a0.z * b.w;
            acc[3][0] += a0.w * b.x; acc[3][1] += a0.w * b.y; acc[3][2] += a0.w * b.z; acc[3][3] += a0.w * b.w;
            acc[4][0] += a1.x * b.x; acc[4][1] += a1.x * b.y; acc[4][2] += a1.x * b.z; acc[4][3] += a1.x * b.w;
            acc[5][0] += a1.y * b.x; acc[5][1] += a1.y * b.y; acc[5][2] += a1.y * b.z; acc[5][3] += a1.y * b.w;
            acc[6][0] += a1.z * b.x; acc[6][1] += a1.z * b.y; acc[6][2] += a1.z * b.z; acc[6][3] += a1.z * b.w;
            acc[7][0] += a1.w * b.x; acc[7][1] += a1.w * b.y; acc[7][2] += a1.w * b.z; acc[7][3] += a1.w * b.w;
        }
        __syncthreads();
    }

    // Epilogue: add bias, vectorized store
    float4 bias = *(const float4*)&Wb[h0 + tx * 4];
    #pragma unroll
    for (int r = 0; r < 8; r++) {
        float4 o;
        o.x = acc[r][0] + bias.x;
        o.y = acc[r][1] + bias.y;
        o.z = acc[r][2] + bias.z;
        o.w = acc[r][3] + bias.w;
        *(float4*)&g_xw[(i0 + ty * 8 + r) * H_ + h0 + tx * 4] = o;
    }
}

// ---------------------------------------------------------------------------
// Kernel 2: sequential scan. One CTA per batch element, 256 threads.
// Thread tid owns output column h = tid.
//   k in [0,UREG): Uw column values register-resident.
//   k in [UREG,256): Uw rows in shared memory, interleaved float2 pairs.
// v double-buffered in shared, read via broadcast float4 with explicit
// software pipelining; 8 accumulators.
// ---------------------------------------------------------------------------
#define UREG 192
#define USM  (H_ - UREG)    // 64 rows in smem

// dynamic smem: [ u2: (USM/2)*H_ float2 ][ v: 2*H_ float ]
#define SCAN_SMEM_BYTES ((USM * H_ + 2 * H_) * 4)

__global__ __launch_bounds__(256, 1) void rnn_scan(const float* __restrict__ Ub,
                                                   float* __restrict__ Out,     // [B,S,H]
                                                   float* __restrict__ Tfin) {  // [B,H]
    extern __shared__ float sm[];
    float2* u2  = (float2*)sm;                 // (USM/2) row-pairs x H_ columns
    float*  vsm = sm + (size_t)USM * H_;       // 2 x H_ double buffer

    const int tid = threadIdx.x;
    const int b   = blockIdx.x;

    // Register-cache rows [0,UREG) of UwT: uw[j] = Uw[tid][j]
    float uw[UREG];
    #pragma unroll
    for (int j = 0; j < UREG; j++)
        uw[j] = g_UwT[j * H_ + tid];

    // Fill smem with rows [UREG,256), interleaved as float2 (2 rows per load)
    for (int r2 = 0; r2 < USM / 2; r2++) {
        float a = g_UwT[(UREG + 2 * r2 + 0) * H_ + tid];
        float c = g_UwT[(UREG + 2 * r2 + 1) * H_ + tid];
        u2[r2 * H_ + tid] = make_float2(a, c);
    }
    __syncthreads();

    const float ub = Ub[tid];
    float t = 0.0f;

    const float* xwp = g_xw + (size_t)b * S_ * H_ + tid;
    float*       op  = Out  + (size_t)b * S_ * H_ + tid;

    float xv = __ldcs(xwp);

    for (int s = 0; s < S_; s++) {
        float v = tanhf(xv + t);
        float* vb = vsm + (s & 1) * H_;
        vb[tid] = v;
        __syncthreads();

        if (s + 1 < S_) xv = __ldcs(xwp + (size_t)(s + 1) * H_);

        const float4* v4 = (const float4*)vb;
        float a0 = ub, a1 = 0.f, a2 = 0.f, a3 = 0.f;
        float a4 = 0.f, a5 = 0.f, a6 = 0.f, a7 = 0.f;

        float4 vA = v4[0];
        float4 vB = v4[1];

        // Register section: rows [0,192) = 48 float4 groups, pipelined
        #pragma unroll
        for (int q = 0; q < 48; q += 2) {
            float4 nA = v4[q + 2];
            float4 nB = v4[q + 3];
            const int j = 4 * q;
            a0 += uw[j + 0] * vA.x;  a1 += uw[j + 1] * vA.y;
            a2 += uw[j + 2] * vA.z;  a3 += uw[j + 3] * vA.w;
            a4 += uw[j + 4] * vB.x;  a5 += uw[j + 5] * vB.y;
            a6 += uw[j + 6] * vB.z;  a7 += uw[j + 7] * vB.w;
            vA = nA; vB = nB;
        }

        // Shared-memory section: rows [192,256) = 16 float4 groups
        // (vA = v4[48], vB = v4[49] on entry)
        const float2* up = u2 + tid;
        #pragma unroll
        for (int q = 48; q < 64; q += 2) {
            float4 nA, nB;
            if (q + 2 < 64) { nA = v4[q + 2]; nB = v4[q + 3]; }
            else            { nA = vA;        nB = vB;        }
            const int r2b = (4 * q - UREG) >> 1;   // row-pair index
            float2 u0 = up[(r2b + 0) * H_];
            float2 u1 = up[(r2b + 1) * H_];
            float2 uu2 = up[(r2b + 2) * H_];
            float2 u3 = up[(r2b + 3) * H_];
            a0 += u0.x * vA.x;  a1 += u0.y * vA.y;
            a2 += u1.x * vA.z;  a3 += u1.y * vA.w;
            a4 += uu2.x * vB.x; a5 += uu2.y * vB.y;
            a6 += u3.x * vB.z;  a7 += u3.y * vB.w;
            vA = nA; vB = nB;
        }

        t = ((a0 + a1) + (a2 + a3)) + ((a4 + a5) + (a6 + a7));
        op[(size_t)s * H_] = t;
    }

    Tfin[b * H_ + tid] = t;
}

// ---------------------------------------------------------------------------
// Launcher
// ---------------------------------------------------------------------------
extern "C" void kernel_launch(void* const* d_in, const int* in_sizes, int n_in,
                              void* d_out, int out_size) {
    const float* x  = (const float*)d_in[0];   // [B,S,E]
    const float* Ww = (const float*)d_in[1];   // [H,E]
    const float* Wb = (const float*)d_in[2];   // [H]
    const float* Uw = (const float*)d_in[3];   // [H,H]
    const float* Ub = (const float*)d_in[4];   // [H]

    float* out  = (float*)d_out;
    float* tfin = out;                          // [B,H]   (tuple element 0)
    float* O    = out + (size_t)B_ * H_;        // [B,S,H] (tuple element 1)

    cudaFuncSetAttribute(rnn_scan, cudaFuncAttributeMaxDynamicSharedMemorySize,
                         SCAN_SMEM_BYTES);

    transpose256<<<H_, H_>>>(Uw);
    gemm_xw<<<dim3(H_ / GTN, (B_ * S_) / GTM), 256>>>(x, Ww, Wb);
    rnn_scan<<<B_, 256, SCAN_SMEM_BYTES>>>(Ub, O, tfin);
}